// round 1
// baseline (speedup 1.0000x reference)
#include <cuda_runtime.h>
#include <cstdint>

#define V_N 65536
#define E_N 4096
#define P_N 4096
#define T_N 512
#define SENTF 1000000000.0f
#define BIGF  1e30f
#define INFF  __int_as_float(0x7f800000)

// Scratch (device globals: no allocations allowed)
__device__ float2 g_passA[E_N];   // (xmn, xmx)
__device__ float4 g_passB[E_N];   // (ymn, ymx, b, 1/a)
__device__ float2 g_ab[E_N];      // (a, b)
__device__ float4 g_tbl[T_N];     // TableR cols 3..6
__device__ float  g_m[P_N];
__device__ int    g_valid[P_N];

// ---------------------------------------------------------------------------
// Kernel 1: per-edge precompute + table extraction
// ---------------------------------------------------------------------------
__global__ void prep_kernel(const float* __restrict__ verts,
                            const float* __restrict__ tableR,
                            const int*   __restrict__ edges) {
    int e = blockIdx.x * blockDim.x + threadIdx.x;
    if (e < T_N) {
        const float* r = tableR + e * 7;
        g_tbl[e] = make_float4(r[3], r[4], r[5], r[6]);
    }
    if (e < E_N) {
        int i0 = edges[2 * e + 0];
        int i1 = edges[2 * e + 1];
        float x0 = verts[3 * i0 + 0], y0 = verts[3 * i0 + 1];
        float x1 = verts[3 * i1 + 0], y1 = verts[3 * i1 + 1];
        float a = (y0 - y1) / (x0 - x1);                 // IEEE div (matches ref)
        float b = __fsub_rn(y0, __fmul_rn(a, x0));       // no FMA contraction
        g_passA[e] = make_float2(fminf(x0, x1), fmaxf(x0, x1));
        g_passB[e] = make_float4(fminf(y0, y1), fmaxf(y0, y1), b, 1.0f / a);
        g_ab[e]    = make_float2(a, b);
    }
}

// ---------------------------------------------------------------------------
// Kernel 2: warp-per-point; compute m[p] and valid[p]
// ---------------------------------------------------------------------------
__global__ void __launch_bounds__(256) point_kernel(
        const float* __restrict__ verts,
        const int*   __restrict__ listAll) {
    const unsigned FULL = 0xffffffffu;
    int lane = threadIdx.x & 31;
    int warp = threadIdx.x >> 5;
    int p = blockIdx.x * 8 + warp;   // 512 blocks * 8 warps = 4096 points

    int li = __ldg(&listAll[p]);
    float px = __ldg(&verts[3 * li + 0]);
    float py = __ldg(&verts[3 * li + 1]);

    // ---- Pass 1: first edge index with px strictly inside (xmn, xmx) ----
    int idx = 0x7fffffff;
    for (int e = lane; e < E_N; e += 32) {
        float2 mm = __ldg(&g_passA[e]);
        if (px > mm.x && px < mm.y) { idx = e; break; }  // lane stream is ascending
    }
    #pragma unroll
    for (int o = 16; o; o >>= 1)
        idx = min(idx, __shfl_xor_sync(FULL, idx, o));
    if (idx == 0x7fffffff) idx = E_N - 1;

    float2 ab = __ldg(&g_ab[idx]);
    float exposeY = __fadd_rn(__fmul_rn(ab.x, px), ab.y);  // no FMA: match XLA
    float L1 = fabsf(py - exposeY);
    float cy = (py + exposeY) * 0.5f;

    // ---- Pass 2: condB reductions over all edges ----
    int n = 0, hs = 0, hi = 0;
    float xallmx = -SENTF, xallmn = SENTF;   // where-fill clamps replicated
    float xs = SENTF, xinf = -SENTF;
    #pragma unroll 4
    for (int e = lane; e < E_N; e += 32) {
        float4 q = __ldg(&g_passB[e]);       // (ymn, ymx, b, inv_a)
        if (cy > q.x && cy < q.y) {
            float xi = __fmul_rn(__fsub_rn(cy, q.z), q.w);
            n++;
            xallmx = fmaxf(xallmx, xi);
            xallmn = fminf(xallmn, xi);
            if (xi >= px) { hs = 1; xs   = fminf(xs,   xi); }
            else          { hi = 1; xinf = fmaxf(xinf, xi); }
        }
    }
    #pragma unroll
    for (int o = 16; o; o >>= 1) {
        n      +=       __shfl_xor_sync(FULL, n,      o);
        xallmx = fmaxf(xallmx, __shfl_xor_sync(FULL, xallmx, o));
        xallmn = fminf(xallmn, __shfl_xor_sync(FULL, xallmn, o));
        xs     = fminf(xs,     __shfl_xor_sync(FULL, xs,     o));
        xinf   = fmaxf(xinf,   __shfl_xor_sync(FULL, xinf,   o));
        hs     |=       __shfl_xor_sync(FULL, hs,     o);
        hi     |=       __shfl_xor_sync(FULL, hi,     o);
    }

    int valid = (n == 2) || (n > 2 && hs && hi);
    float dx  = (n == 2) ? (xallmx - xallmn) : (xs - xinf);
    float L2  = fabsf(dx);
    float d1  = fabsf(cy - 1.0f);
    float d2  = fabsf(px - 1.0f);

    // ---- Table min over T=512 rows ----
    float pm = INFF;
    #pragma unroll 4
    for (int t = lane; t < T_N; t += 32) {
        float4 r = __ldg(&g_tbl[t]);
        float al = fabsf(L1 - r.x) + fabsf(L2 - r.y)
                 + fabsf(d1 - r.z) + fabsf(d2 - r.w);
        pm = fminf(pm, al);
    }
    #pragma unroll
    for (int o = 16; o; o >>= 1)
        pm = fminf(pm, __shfl_xor_sync(FULL, pm, o));

    if (lane == 0) {
        g_m[p]     = valid ? pm : BIGF;
        g_valid[p] = valid;
    }
}

// ---------------------------------------------------------------------------
// Kernel 3: cummin over P + masked sum  (single block)
// ---------------------------------------------------------------------------
__global__ void __launch_bounds__(1024) scan_kernel(float* __restrict__ out) {
    __shared__ float s[1024];
    int tid = threadIdx.x;
    int base = tid * 4;

    float m0 = g_m[base + 0], m1 = g_m[base + 1];
    float m2 = g_m[base + 2], m3 = g_m[base + 3];
    int v0 = g_valid[base + 0], v1 = g_valid[base + 1];
    int v2 = g_valid[base + 2], v3 = g_valid[base + 3];

    // local inclusive cummin within the 4-element chunk
    float c0 = m0;
    float c1 = fminf(c0, m1);
    float c2 = fminf(c1, m2);
    float c3 = fminf(c2, m3);

    s[tid] = c3;
    __syncthreads();

    // inclusive min-scan over 1024 chunk minima (Hillis-Steele)
    for (int off = 1; off < 1024; off <<= 1) {
        float v = s[tid];
        if (tid >= off) v = fminf(v, s[tid - off]);
        __syncthreads();
        s[tid] = v;
        __syncthreads();
    }

    float pre = (tid > 0) ? s[tid - 1] : INFF;   // exclusive prefix for this chunk

    float acc = 0.0f;
    if (v0) acc += fminf(pre, c0);
    if (v1) acc += fminf(pre, c1);
    if (v2) acc += fminf(pre, c2);
    if (v3) acc += fminf(pre, c3);

    __syncthreads();
    s[tid] = acc;
    __syncthreads();
    for (int off = 512; off > 0; off >>= 1) {
        if (tid < off) s[tid] += s[tid + off];
        __syncthreads();
    }
    if (tid == 0) out[0] = s[0];
}

// ---------------------------------------------------------------------------
extern "C" void kernel_launch(void* const* d_in, const int* in_sizes, int n_in,
                              void* d_out, int out_size) {
    const float* verts   = (const float*)d_in[0];
    const float* tableR  = (const float*)d_in[1];
    const int*   edges   = (const int*)  d_in[2];
    const int*   listAll = (const int*)  d_in[3];
    // d_in[4] = epoch, d_in[5] = pth : unused by the reference math

    prep_kernel <<<16,  256>>>(verts, tableR, edges);
    point_kernel<<<512, 256>>>(verts, listAll);
    scan_kernel <<<1,  1024>>>((float*)d_out);
}